// round 3
// baseline (speedup 1.0000x reference)
#include <cuda_runtime.h>
#include <cuda_bf16.h>

// Problem constants (fixed by the reference)
#define Nn 50000
#define Ne 800000
// IN=128, H1=8, HID=32, OUT=64

// ---------------- device scratch (static allocation, allowed) ----------------
__device__ float g_h1[(size_t)Nn * 256];   // layer1 projected features [N,8,32]
__device__ float g_x1[(size_t)Nn * 256];   // layer1 output (relu) = layer2 input
__device__ float g_el1[Nn * 8], g_er1[Nn * 8];
__device__ float g_h2[(size_t)Nn * 32];
__device__ float g_el2[Nn], g_er2[Nn];
__device__ float g_h3[(size_t)Nn * 64];
__device__ float g_el3[Nn], g_er3[Nn];

__device__ int g_deg[Nn];
__device__ int g_fill[Nn];
__device__ int g_rowstart[Nn + 1];
__device__ int g_esrc[Ne];                 // src indices sorted (bucketed) by dst

__device__ unsigned g_wpk[128 * 256];      // W1 packed bf16 (lo16=hi part, hi16=lo part)

// ---------------- helpers ----------------
__device__ __forceinline__ float wred(float v) {
#pragma unroll
    for (int o = 16; o > 0; o >>= 1) v += __shfl_xor_sync(0xffffffffu, v, o);
    return v;
}

__device__ __forceinline__ float lrelu(float x) {
    return x > 0.f ? x : 0.2f * x;
}

__device__ __forceinline__ void mma16816(float c[4], unsigned a0, unsigned a1,
                                         unsigned a2, unsigned a3,
                                         unsigned b0, unsigned b1) {
    asm volatile(
        "mma.sync.aligned.m16n8k16.row.col.f32.bf16.bf16.f32 "
        "{%0,%1,%2,%3}, {%4,%5,%6,%7}, {%8,%9}, {%0,%1,%2,%3};\n"
        : "+f"(c[0]), "+f"(c[1]), "+f"(c[2]), "+f"(c[3])
        : "r"(a0), "r"(a1), "r"(a2), "r"(a3), "r"(b0), "r"(b1));
}

// ---------------- CSR build ----------------
__global__ void zero_kernel() {
    int i = blockIdx.x * blockDim.x + threadIdx.x;
    if (i < Nn) { g_deg[i] = 0; g_fill[i] = 0; }
}

__global__ void count_kernel(const int* __restrict__ dst) {
    int e = blockIdx.x * blockDim.x + threadIdx.x;
    if (e < Ne) atomicAdd(&g_deg[dst[e]], 1);
}

// single-block hierarchical exclusive scan of g_deg -> g_rowstart
__global__ void scan_kernel() {
    __shared__ int warpsum[32];
    const int t = threadIdx.x;            // 1024 threads
    const int lane = t & 31, wid = t >> 5;
    const int CH = (Nn + 1023) / 1024;    // 49
    const int base = t * CH;
    int sum = 0;
#pragma unroll 1
    for (int i = 0; i < CH; i++) {
        int idx = base + i;
        if (idx < Nn) sum += g_deg[idx];
    }
    int v = sum;
#pragma unroll
    for (int o = 1; o < 32; o <<= 1) {
        int u = __shfl_up_sync(0xffffffffu, v, o);
        if (lane >= o) v += u;
    }
    if (lane == 31) warpsum[wid] = v;
    __syncthreads();
    if (wid == 0) {
        int w = warpsum[lane];
        int vv = w;
#pragma unroll
        for (int o = 1; o < 32; o <<= 1) {
            int u = __shfl_up_sync(0xffffffffu, vv, o);
            if (lane >= o) vv += u;
        }
        warpsum[lane] = vv;
    }
    __syncthreads();
    int excl = v - sum + (wid > 0 ? warpsum[wid - 1] : 0);
    int run = excl;
#pragma unroll 1
    for (int i = 0; i < CH; i++) {
        int idx = base + i;
        if (idx < Nn) { g_rowstart[idx] = run; run += g_deg[idx]; }
    }
    if (t == 1023) g_rowstart[Nn] = run;
}

__global__ void scatter_kernel(const int* __restrict__ src, const int* __restrict__ dst) {
    int e = blockIdx.x * blockDim.x + threadIdx.x;
    if (e >= Ne) return;
    int d = dst[e];
    int pos = g_rowstart[d] + atomicAdd(&g_fill[d], 1);
    g_esrc[pos] = src[e];
}

// ---------------- W1 bf16 hi/lo packing ----------------
__global__ void wpack_kernel(const float* __restrict__ W) {
    int i = blockIdx.x * blockDim.x + threadIdx.x;   // 32768
    float w = W[i];
    __nv_bfloat16 h = __float2bfloat16(w);
    float hf = __bfloat162float(h);
    __nv_bfloat16 l = __float2bfloat16(w - hf);
    unsigned hb = __bfloat16_as_ushort(h);
    unsigned lb = __bfloat16_as_ushort(l);
    g_wpk[i] = hb | (lb << 16);                       // phys k even = hi, odd = lo
}

// ---------------- layer 1 GEMM via bf16 split-product tensor cores --------
// C[64, 256] per block = X[64,128] @ W[128,256], fp32-accurate (2-pass split).
#define A_STRIDE 132
#define B_STRIDE 264
#define G1_SMEM ((2 * 64 * A_STRIDE + 128 * B_STRIDE) * 4)

__global__ void __launch_bounds__(256) gemm1m_kernel(const float* __restrict__ X) {
    extern __shared__ unsigned smem[];
    unsigned* A1 = smem;                        // (ah, ah) packed, [64][128] pad 132
    unsigned* A2 = smem + 64 * A_STRIDE;        // (al, al) packed
    unsigned* B  = smem + 2 * 64 * A_STRIDE;    // (bh, bl) packed, [128][256] pad 264

    const int t = threadIdx.x;
    const int n0 = blockIdx.x * 64;

    // load & split-pack A tile (64 rows x 128 k fp32)
#pragma unroll
    for (int i = 0; i < 8; i++) {
        int idx = t + 256 * i;                  // float4 index, 2048 total
        int row = idx >> 5, c4 = idx & 31;
        int grow = n0 + row;
        float4 v = (grow < Nn) ? __ldg((const float4*)(X + (size_t)grow * 128) + c4)
                               : make_float4(0.f, 0.f, 0.f, 0.f);
        float vv[4] = {v.x, v.y, v.z, v.w};
        unsigned p1[4], p2[4];
#pragma unroll
        for (int j = 0; j < 4; j++) {
            __nv_bfloat16 h = __float2bfloat16(vv[j]);
            float hf = __bfloat162float(h);
            __nv_bfloat16 l = __float2bfloat16(vv[j] - hf);
            unsigned hb = __bfloat16_as_ushort(h);
            unsigned lb = __bfloat16_as_ushort(l);
            p1[j] = hb | (hb << 16);
            p2[j] = lb | (lb << 16);
        }
        *(uint4*)&A1[row * A_STRIDE + c4 * 4] = make_uint4(p1[0], p1[1], p1[2], p1[3]);
        *(uint4*)&A2[row * A_STRIDE + c4 * 4] = make_uint4(p2[0], p2[1], p2[2], p2[3]);
    }
    // load B (pre-packed W1): 128x256 u32
#pragma unroll
    for (int i = 0; i < 32; i++) {
        int idx = t + 256 * i;                  // uint4 index, 8192 total
        int row = idx >> 6, c4 = idx & 63;
        uint4 v = *((const uint4*)g_wpk + idx);
        *(uint4*)&B[row * B_STRIDE + c4 * 4] = v;
    }
    __syncthreads();

    const int warp = t >> 5, lane = t & 31;
    const int wm = warp >> 2, wn = warp & 3;    // 2 (M) x 4 (N) warps
    const int g = lane >> 2, tr = lane & 3;

    float c[2][8][4] = {};
#pragma unroll 1
    for (int ks = 0; ks < 16; ks++) {
        int kb = ks * 8;                        // logical k base
        unsigned b0[8], b1[8];
#pragma unroll
        for (int nt = 0; nt < 8; nt++) {
            int col = wn * 64 + nt * 8 + g;
            b0[nt] = B[(kb + tr) * B_STRIDE + col];
            b1[nt] = B[(kb + 4 + tr) * B_STRIDE + col];
        }
#pragma unroll
        for (int pass = 0; pass < 2; pass++) {
            const unsigned* Ap = pass ? A2 : A1;
#pragma unroll
            for (int mt = 0; mt < 2; mt++) {
                int rb = wm * 32 + mt * 16;
                unsigned a0 = Ap[(rb + g) * A_STRIDE + kb + tr];
                unsigned a1 = Ap[(rb + 8 + g) * A_STRIDE + kb + tr];
                unsigned a2 = Ap[(rb + g) * A_STRIDE + kb + 4 + tr];
                unsigned a3 = Ap[(rb + 8 + g) * A_STRIDE + kb + 4 + tr];
#pragma unroll
                for (int nt = 0; nt < 8; nt++)
                    mma16816(c[mt][nt], a0, a1, a2, a3, b0[nt], b1[nt]);
            }
        }
    }

    // store C
#pragma unroll
    for (int mt = 0; mt < 2; mt++) {
        int r0 = n0 + wm * 32 + mt * 16 + g;
#pragma unroll
        for (int nt = 0; nt < 8; nt++) {
            int col = wn * 64 + nt * 8 + tr * 2;
            if (r0 < Nn)
                *(float2*)&g_h1[(size_t)r0 * 256 + col] = make_float2(c[mt][nt][0], c[mt][nt][1]);
            if (r0 + 8 < Nn)
                *(float2*)&g_h1[(size_t)(r0 + 8) * 256 + col] = make_float2(c[mt][nt][2], c[mt][nt][3]);
        }
    }
}

// ---------------- layer 1 el/er: warp per node over g_h1 ----------------
__global__ void elr1_kernel(const float* __restrict__ al, const float* __restrict__ ar) {
    const int wid = (blockIdx.x * blockDim.x + threadIdx.x) >> 5;
    const int lane = threadIdx.x & 31;
    if (wid >= Nn) return;
    const float4* hp = (const float4*)(g_h1 + (size_t)wid * 256);
    float4 h0 = hp[lane * 2], h1 = hp[lane * 2 + 1];
    float4 a0 = __ldg((const float4*)al + lane * 2);
    float4 a1 = __ldg((const float4*)al + lane * 2 + 1);
    float4 r0 = __ldg((const float4*)ar + lane * 2);
    float4 r1 = __ldg((const float4*)ar + lane * 2 + 1);
    float e = h0.x * a0.x + h0.y * a0.y + h0.z * a0.z + h0.w * a0.w
            + h1.x * a1.x + h1.y * a1.y + h1.z * a1.z + h1.w * a1.w;
    float r = h0.x * r0.x + h0.y * r0.y + h0.z * r0.z + h0.w * r0.w
            + h1.x * r1.x + h1.y * r1.y + h1.z * r1.z + h1.w * r1.w;
    e += __shfl_xor_sync(0xffffffffu, e, 1);
    e += __shfl_xor_sync(0xffffffffu, e, 2);
    r += __shfl_xor_sync(0xffffffffu, r, 1);
    r += __shfl_xor_sync(0xffffffffu, r, 2);
    if ((lane & 3) == 0) {
        g_el1[wid * 8 + (lane >> 2)] = e;
        g_er1[wid * 8 + (lane >> 2)] = r;
    }
}

// ---------------- layer 1 aggregation: warp per dst, 8 heads x 32 feat ----
__global__ void agg1_kernel(const float* __restrict__ b1) {
    const int wid = (blockIdx.x * blockDim.x + threadIdx.x) >> 5;
    const int lane = threadIdx.x & 31;
    if (wid >= Nn) return;
    const int d = wid;
    const int rs = g_rowstart[d], re = g_rowstart[d + 1];
    const float erh = (lane < 8) ? g_er1[d * 8 + lane] : 0.f;
    float acc[8] = {0, 0, 0, 0, 0, 0, 0, 0};
    float s = 0.f;
    for (int e = rs; e < re; e++) {
        int src = g_esrc[e];
        float ee = 0.f;
        if (lane < 8) {
            float lg = lrelu(g_el1[src * 8 + lane] + erh);
            ee = __expf(lg);
            s += ee;
        }
        const float* hp = g_h1 + (size_t)src * 256;
#pragma unroll
        for (int h = 0; h < 8; h++) {
            float eh = __shfl_sync(0xffffffffu, ee, h);
            acc[h] = fmaf(eh, hp[h * 32 + lane], acc[h]);
        }
    }
#pragma unroll
    for (int h = 0; h < 8; h++) {
        float sh = __shfl_sync(0xffffffffu, s, h);
        float v = (sh > 0.f) ? acc[h] / sh : 0.f;
        v += b1[h * 32 + lane];
        g_x1[(size_t)d * 256 + h * 32 + lane] = fmaxf(v, 0.f);  // relu
    }
}

// ---------------- layer 2: GEMM [N,256]@[256,32] + el/er ----------------
__global__ void gemm2_kernel(const float* __restrict__ W,
                             const float* __restrict__ al, const float* __restrict__ ar) {
    __shared__ float xs[8 * 256];
    const int t = threadIdx.x;      // 256
    const int n0 = blockIdx.x * 8;
#pragma unroll
    for (int r = 0; r < 8; r++) xs[t + 256 * r] = g_x1[(size_t)n0 * 256 + t + 256 * r];
    __syncthreads();
    const int i = t >> 5, c = t & 31;
    const float* xr = xs + i * 256;
    float acc = 0.f;
#pragma unroll 8
    for (int k = 0; k < 256; k++) acc = fmaf(xr[k], __ldg(&W[k * 32 + c]), acc);
    const int n = n0 + i;
    g_h2[(size_t)n * 32 + c] = acc;
    float e = wred(acc * al[c]);
    float r = wred(acc * ar[c]);
    if (c == 0) { g_el2[n] = e; g_er2[n] = r; }
}

// ---------------- layer 2 aggregation ----------------
__global__ void agg2_kernel(const float* __restrict__ b2, float* __restrict__ emb) {
    const int wid = (blockIdx.x * blockDim.x + threadIdx.x) >> 5;
    const int lane = threadIdx.x & 31;
    if (wid >= Nn) return;
    const int d = wid;
    const int rs = g_rowstart[d], re = g_rowstart[d + 1];
    const float erd = g_er2[d];
    float acc = 0.f, s = 0.f;
    for (int e = rs; e < re; e++) {
        int src = g_esrc[e];
        float ee = __expf(lrelu(g_el2[src] + erd));
        s += ee;
        acc = fmaf(ee, g_h2[(size_t)src * 32 + lane], acc);
    }
    float v = (s > 0.f) ? acc / s : 0.f;
    emb[(size_t)d * 32 + lane] = v + b2[lane];
}

// ---------------- layer 3: GEMM [N,32]@[32,64] + el/er ----------------
__global__ void gemm3_kernel(const float* __restrict__ X, const float* __restrict__ W,
                             const float* __restrict__ al, const float* __restrict__ ar) {
    __shared__ float xs[4 * 32];
    __shared__ float sm_e[8], sm_r[8];
    const int t = threadIdx.x;      // 256
    const int n0 = blockIdx.x * 4;
    if (t < 128) xs[t] = X[(size_t)n0 * 32 + t];
    __syncthreads();
    const int i = t >> 6, c = t & 63;
    float acc = 0.f;
#pragma unroll
    for (int k = 0; k < 32; k++) acc = fmaf(xs[i * 32 + k], __ldg(&W[k * 64 + c]), acc);
    const int n = n0 + i;
    g_h3[(size_t)n * 64 + c] = acc;
    float e = wred(acc * al[c]);
    float r = wred(acc * ar[c]);
    const int warp = t >> 5, lane = t & 31;
    if (lane == 0) { sm_e[warp] = e; sm_r[warp] = r; }
    __syncthreads();
    if (t < 4) {
        g_el3[n0 + t] = sm_e[2 * t] + sm_e[2 * t + 1];
        g_er3[n0 + t] = sm_r[2 * t] + sm_r[2 * t + 1];
    }
}

// ---------------- layer 3 aggregation ----------------
__global__ void agg3_kernel(const float* __restrict__ b3, float* __restrict__ out) {
    const int wid = (blockIdx.x * blockDim.x + threadIdx.x) >> 5;
    const int lane = threadIdx.x & 31;
    if (wid >= Nn) return;
    const int d = wid;
    const int rs = g_rowstart[d], re = g_rowstart[d + 1];
    const float erd = g_er3[d];
    float acc0 = 0.f, acc1 = 0.f, s = 0.f;
    for (int e = rs; e < re; e++) {
        int src = g_esrc[e];
        float ee = __expf(lrelu(g_el3[src] + erd));
        s += ee;
        const float* hp = g_h3 + (size_t)src * 64;
        acc0 = fmaf(ee, hp[lane], acc0);
        acc1 = fmaf(ee, hp[32 + lane], acc1);
    }
    float inv = (s > 0.f) ? (1.f / s) : 0.f;
    out[(size_t)d * 64 + lane]      = acc0 * inv + b3[lane];
    out[(size_t)d * 64 + 32 + lane] = acc1 * inv + b3[32 + lane];
}

// ---------------- launch ----------------
extern "C" void kernel_launch(void* const* d_in, const int* in_sizes, int n_in,
                              void* d_out, int out_size) {
    const float* features = (const float*)d_in[0];
    const int*   src      = (const int*)d_in[1];
    const int*   dst      = (const int*)d_in[2];
    const float* W1  = (const float*)d_in[3];
    const float* al1 = (const float*)d_in[4];
    const float* ar1 = (const float*)d_in[5];
    const float* b1  = (const float*)d_in[6];
    const float* W2  = (const float*)d_in[7];
    const float* al2 = (const float*)d_in[8];
    const float* ar2 = (const float*)d_in[9];
    const float* b2  = (const float*)d_in[10];
    const float* W3  = (const float*)d_in[11];
    const float* al3 = (const float*)d_in[12];
    const float* ar3 = (const float*)d_in[13];
    const float* b3  = (const float*)d_in[14];

    float* out = (float*)d_out;                 // h: [N,64] first
    float* emb = out + (size_t)Nn * 64;         // embedding: [N,32] second

    static bool attr_set = false;
    if (!attr_set) {
        cudaFuncSetAttribute(gemm1m_kernel, cudaFuncAttributeMaxDynamicSharedMemorySize, G1_SMEM);
        attr_set = true;
    }

    // CSR build (graph identical across layers)
    zero_kernel<<<(Nn + 255) / 256, 256>>>();
    count_kernel<<<(Ne + 255) / 256, 256>>>(dst);
    scan_kernel<<<1, 1024>>>();
    scatter_kernel<<<(Ne + 255) / 256, 256>>>(src, dst);

    // layer 1
    wpack_kernel<<<128, 256>>>(W1);
    gemm1m_kernel<<<(Nn + 63) / 64, 256, G1_SMEM>>>(features);
    elr1_kernel<<<(Nn + 7) / 8, 256>>>(al1, ar1);
    agg1_kernel<<<Nn / 8, 256>>>(b1);
    // layer 2
    gemm2_kernel<<<Nn / 8, 256>>>(W2, al2, ar2);
    agg2_kernel<<<Nn / 8, 256>>>(b2, emb);
    // layer 3
    gemm3_kernel<<<Nn / 4, 256>>>(emb, W3, al3, ar3);
    agg3_kernel<<<Nn / 8, 256>>>(b3, out);
}

// round 4
// speedup vs baseline: 1.0488x; 1.0488x over previous
#include <cuda_runtime.h>
#include <cuda_fp16.h>
#include <cuda_bf16.h>

// Problem constants (fixed by the reference)
#define Nn 50000
#define Ne 800000
// IN=128, H1=8, HID=32, OUT=64

// ---------------- device scratch ----------------
__device__ __half g_h1h[(size_t)Nn * 256];  // layer1 projected features fp16 [N,8,32]
__device__ float g_x1[(size_t)Nn * 256];    // layer1 output (relu) = layer2 input
__device__ float g_el1[Nn * 8], g_er1[Nn * 8];
__device__ float g_h2[(size_t)Nn * 32];
__device__ float g_el2[Nn], g_er2[Nn];
__device__ float g_h3[(size_t)Nn * 64];
__device__ float g_el3[Nn], g_er3[Nn];

__device__ int g_deg[Nn];
__device__ int g_fill[Nn];
__device__ int g_rowstart[Nn + 1];
__device__ int g_esrc[Ne];                 // src indices bucketed by dst

__device__ unsigned g_wpk[128 * 256];      // W1 packed bf16 (lo16=hi part, hi16=lo part)
__device__ unsigned g_wpk2[256 * 32];      // W2 packed bf16

// ---------------- helpers ----------------
__device__ __forceinline__ float wred(float v) {
#pragma unroll
    for (int o = 16; o > 0; o >>= 1) v += __shfl_xor_sync(0xffffffffu, v, o);
    return v;
}

__device__ __forceinline__ float lrelu(float x) {
    return x > 0.f ? x : 0.2f * x;
}

__device__ __forceinline__ void mma16816(float c[4], unsigned a0, unsigned a1,
                                         unsigned a2, unsigned a3,
                                         unsigned b0, unsigned b1) {
    asm volatile(
        "mma.sync.aligned.m16n8k16.row.col.f32.bf16.bf16.f32 "
        "{%0,%1,%2,%3}, {%4,%5,%6,%7}, {%8,%9}, {%0,%1,%2,%3};\n"
        : "+f"(c[0]), "+f"(c[1]), "+f"(c[2]), "+f"(c[3])
        : "r"(a0), "r"(a1), "r"(a2), "r"(a3), "r"(b0), "r"(b1));
}

__device__ __forceinline__ void splitpack(float v, unsigned& dup_hi, unsigned& dup_lo) {
    __nv_bfloat16 h = __float2bfloat16(v);
    float hf = __bfloat162float(h);
    __nv_bfloat16 l = __float2bfloat16(v - hf);
    unsigned hb = __bfloat16_as_ushort(h);
    unsigned lb = __bfloat16_as_ushort(l);
    dup_hi = hb | (hb << 16);
    dup_lo = lb | (lb << 16);
}

// ---------------- CSR build ----------------
__global__ void zero_kernel() {
    int i = blockIdx.x * blockDim.x + threadIdx.x;
    if (i < Nn) { g_deg[i] = 0; g_fill[i] = 0; }
}

__global__ void count_kernel(const int* __restrict__ dst) {
    int e = blockIdx.x * blockDim.x + threadIdx.x;
    if (e < Ne) atomicAdd(&g_deg[dst[e]], 1);
}

__global__ void scan_kernel() {
    __shared__ int warpsum[32];
    const int t = threadIdx.x;            // 1024 threads
    const int lane = t & 31, wid = t >> 5;
    const int CH = (Nn + 1023) / 1024;
    const int base = t * CH;
    int sum = 0;
#pragma unroll 1
    for (int i = 0; i < CH; i++) {
        int idx = base + i;
        if (idx < Nn) sum += g_deg[idx];
    }
    int v = sum;
#pragma unroll
    for (int o = 1; o < 32; o <<= 1) {
        int u = __shfl_up_sync(0xffffffffu, v, o);
        if (lane >= o) v += u;
    }
    if (lane == 31) warpsum[wid] = v;
    __syncthreads();
    if (wid == 0) {
        int w = warpsum[lane];
        int vv = w;
#pragma unroll
        for (int o = 1; o < 32; o <<= 1) {
            int u = __shfl_up_sync(0xffffffffu, vv, o);
            if (lane >= o) vv += u;
        }
        warpsum[lane] = vv;
    }
    __syncthreads();
    int excl = v - sum + (wid > 0 ? warpsum[wid - 1] : 0);
    int run = excl;
#pragma unroll 1
    for (int i = 0; i < CH; i++) {
        int idx = base + i;
        if (idx < Nn) { g_rowstart[idx] = run; run += g_deg[idx]; }
    }
    if (t == 1023) g_rowstart[Nn] = run;
}

__global__ void scatter_kernel(const int* __restrict__ src, const int* __restrict__ dst) {
    int e = blockIdx.x * blockDim.x + threadIdx.x;
    if (e >= Ne) return;
    int d = dst[e];
    int pos = g_rowstart[d] + atomicAdd(&g_fill[d], 1);
    g_esrc[pos] = src[e];
}

// ---------------- W packing (bf16 hi/lo) ----------------
__global__ void wpack_kernel(const float* __restrict__ W) {
    int i = blockIdx.x * blockDim.x + threadIdx.x;   // 32768
    float w = W[i];
    __nv_bfloat16 h = __float2bfloat16(w);
    float hf = __bfloat162float(h);
    __nv_bfloat16 l = __float2bfloat16(w - hf);
    g_wpk[i] = (unsigned)__bfloat16_as_ushort(h) | ((unsigned)__bfloat16_as_ushort(l) << 16);
}

__global__ void wpack2_kernel(const float* __restrict__ W) {
    int i = blockIdx.x * blockDim.x + threadIdx.x;   // 8192
    float w = W[i];
    __nv_bfloat16 h = __float2bfloat16(w);
    float hf = __bfloat162float(h);
    __nv_bfloat16 l = __float2bfloat16(w - hf);
    g_wpk2[i] = (unsigned)__bfloat16_as_ushort(h) | ((unsigned)__bfloat16_as_ushort(l) << 16);
}

// ---------------- layer 1 GEMM (tensor cores, bf16 split) + el/er epilogue ----
#define A_STRIDE 132
#define B_STRIDE 264
#define G1_SMEM ((2 * 64 * A_STRIDE + 128 * B_STRIDE) * 4)

__global__ void __launch_bounds__(256) gemm1m_kernel(const float* __restrict__ X,
                                                     const float* __restrict__ al,
                                                     const float* __restrict__ ar) {
    extern __shared__ unsigned smem[];
    unsigned* A1 = smem;                        // (ah, ah), [64][128] pad 132
    unsigned* A2 = smem + 64 * A_STRIDE;        // (al, al)
    unsigned* B  = smem + 2 * 64 * A_STRIDE;    // (bh, bl), [128][256] pad 264

    const int t = threadIdx.x;
    const int n0 = blockIdx.x * 64;

    // load & split-pack A tile
#pragma unroll
    for (int i = 0; i < 8; i++) {
        int idx = t + 256 * i;                  // float4 index, 2048 total
        int row = idx >> 5, c4 = idx & 31;
        int grow = n0 + row;
        float4 v = (grow < Nn) ? __ldg((const float4*)(X + (size_t)grow * 128) + c4)
                               : make_float4(0.f, 0.f, 0.f, 0.f);
        float vv[4] = {v.x, v.y, v.z, v.w};
        unsigned p1[4], p2[4];
#pragma unroll
        for (int j = 0; j < 4; j++) splitpack(vv[j], p1[j], p2[j]);
        *(uint4*)&A1[row * A_STRIDE + c4 * 4] = make_uint4(p1[0], p1[1], p1[2], p1[3]);
        *(uint4*)&A2[row * A_STRIDE + c4 * 4] = make_uint4(p2[0], p2[1], p2[2], p2[3]);
    }
    // load B (pre-packed W1)
#pragma unroll
    for (int i = 0; i < 32; i++) {
        int idx = t + 256 * i;                  // uint4 index, 8192 total
        int row = idx >> 6, c4 = idx & 63;
        uint4 v = *((const uint4*)g_wpk + idx);
        *(uint4*)&B[row * B_STRIDE + c4 * 4] = v;
    }
    __syncthreads();

    const int warp = t >> 5, lane = t & 31;
    const int wm = warp >> 2, wn = warp & 3;    // 2 (M) x 4 (N)
    const int g = lane >> 2, tr = lane & 3;

    float c[2][8][4] = {};
#pragma unroll 1
    for (int ks = 0; ks < 16; ks++) {
        int kb = ks * 8;
        unsigned b0[8], b1[8];
#pragma unroll
        for (int nt = 0; nt < 8; nt++) {
            int col = wn * 64 + nt * 8 + g;
            b0[nt] = B[(kb + tr) * B_STRIDE + col];
            b1[nt] = B[(kb + 4 + tr) * B_STRIDE + col];
        }
#pragma unroll
        for (int pass = 0; pass < 2; pass++) {
            const unsigned* Ap = pass ? A2 : A1;
#pragma unroll
            for (int mt = 0; mt < 2; mt++) {
                int rb = wm * 32 + mt * 16;
                unsigned a0 = Ap[(rb + g) * A_STRIDE + kb + tr];
                unsigned a1 = Ap[(rb + 8 + g) * A_STRIDE + kb + tr];
                unsigned a2 = Ap[(rb + g) * A_STRIDE + kb + 4 + tr];
                unsigned a3 = Ap[(rb + 8 + g) * A_STRIDE + kb + 4 + tr];
#pragma unroll
                for (int nt = 0; nt < 8; nt++)
                    mma16816(c[mt][nt], a0, a1, a2, a3, b0[nt], b1[nt]);
            }
        }
    }

    // attention vectors for this warp's 64 columns
    float alv[8][2], arv[8][2];
#pragma unroll
    for (int nt = 0; nt < 8; nt++) {
        int col = wn * 64 + nt * 8 + tr * 2;
        alv[nt][0] = __ldg(al + col);  alv[nt][1] = __ldg(al + col + 1);
        arv[nt][0] = __ldg(ar + col);  arv[nt][1] = __ldg(ar + col + 1);
    }

    // store C (fp16) + el/er epilogue (fp32 accumulators)
#pragma unroll
    for (int mt = 0; mt < 2; mt++) {
#pragma unroll
        for (int half = 0; half < 2; half++) {
            int r = n0 + wm * 32 + mt * 16 + g + 8 * half;
            float pe0 = 0.f, pe1 = 0.f, pr0 = 0.f, pr1 = 0.f;
#pragma unroll
            for (int nt = 0; nt < 8; nt++) {
                float c0 = c[mt][nt][2 * half], c1 = c[mt][nt][2 * half + 1];
                int col = wn * 64 + nt * 8 + tr * 2;
                if (r < Nn)
                    *(__half2*)&g_h1h[(size_t)r * 256 + col] =
                        __floats2half2_rn(c0, c1);
                float pe = c0 * alv[nt][0] + c1 * alv[nt][1];
                float pr = c0 * arv[nt][0] + c1 * arv[nt][1];
                if (nt < 4) { pe0 += pe; pr0 += pr; }
                else        { pe1 += pe; pr1 += pr; }
            }
            pe0 += __shfl_xor_sync(0xffffffffu, pe0, 1);
            pe0 += __shfl_xor_sync(0xffffffffu, pe0, 2);
            pe1 += __shfl_xor_sync(0xffffffffu, pe1, 1);
            pe1 += __shfl_xor_sync(0xffffffffu, pe1, 2);
            pr0 += __shfl_xor_sync(0xffffffffu, pr0, 1);
            pr0 += __shfl_xor_sync(0xffffffffu, pr0, 2);
            pr1 += __shfl_xor_sync(0xffffffffu, pr1, 1);
            pr1 += __shfl_xor_sync(0xffffffffu, pr1, 2);
            if (tr == 0 && r < Nn) {
                g_el1[r * 8 + 2 * wn]     = pe0;
                g_el1[r * 8 + 2 * wn + 1] = pe1;
                g_er1[r * 8 + 2 * wn]     = pr0;
                g_er1[r * 8 + 2 * wn + 1] = pr1;
            }
        }
    }
}

// ---------------- layer 1 aggregation: warp per dst, fp16 gather ----------
__global__ void agg1_kernel(const float* __restrict__ b1) {
    const int wid = (blockIdx.x * blockDim.x + threadIdx.x) >> 5;
    const int lane = threadIdx.x & 31;
    if (wid >= Nn) return;
    const int d = wid;
    const int rs = g_rowstart[d], re = g_rowstart[d + 1];
    const float erh = (lane < 8) ? g_er1[d * 8 + lane] : 0.f;
    // lane owns cols {64q + 2*lane, +1}, q = 0..3; head(q) = 2q + (lane>>4)
    const int h0 = lane >> 4;
    float2 acc[4] = {{0, 0}, {0, 0}, {0, 0}, {0, 0}};
    float s = 0.f;
    for (int e = rs; e < re; e++) {
        int src = g_esrc[e];
        float ee = 0.f;
        if (lane < 8) {
            float lg = lrelu(g_el1[src * 8 + lane] + erh);
            ee = __expf(lg);
            s += ee;
        }
        const __half2* hp = (const __half2*)(g_h1h + (size_t)src * 256);
#pragma unroll
        for (int q = 0; q < 4; q++) {
            float eh = __shfl_sync(0xffffffffu, ee, 2 * q + h0);
            float2 f = __half22float2(hp[q * 32 + lane]);
            acc[q].x = fmaf(eh, f.x, acc[q].x);
            acc[q].y = fmaf(eh, f.y, acc[q].y);
        }
    }
#pragma unroll
    for (int q = 0; q < 4; q++) {
        float sh = __shfl_sync(0xffffffffu, s, 2 * q + h0);
        float inv = (sh > 0.f) ? (1.f / sh) : 0.f;
        int col = 64 * q + 2 * lane;
        float vx = fmaxf(acc[q].x * inv + __ldg(b1 + col), 0.f);
        float vy = fmaxf(acc[q].y * inv + __ldg(b1 + col + 1), 0.f);
        *(float2*)&g_x1[(size_t)d * 256 + col] = make_float2(vx, vy);
    }
}

// ---------------- layer 2 GEMM (tensor cores, bf16 split): [N,256]@[256,32] ----
#define A2_STRIDE 260
#define B2_STRIDE 40
#define G2_SMEM ((2 * 64 * A2_STRIDE + 256 * B2_STRIDE) * 4)

__global__ void __launch_bounds__(256) gemm2m_kernel() {
    extern __shared__ unsigned smem[];
    unsigned* A1 = smem;
    unsigned* A2 = smem + 64 * A2_STRIDE;
    unsigned* B  = smem + 2 * 64 * A2_STRIDE;   // [256][32] pad 40

    const int t = threadIdx.x;
    const int n0 = blockIdx.x * 64;

    // load & split-pack A tile (64 x 256 fp32 from g_x1)
#pragma unroll
    for (int i = 0; i < 16; i++) {
        int idx = t + 256 * i;                  // float4 index, 4096 total
        int row = idx >> 6, c4 = idx & 63;
        int grow = n0 + row;
        float4 v = (grow < Nn) ? *((const float4*)(g_x1 + (size_t)grow * 256) + c4)
                               : make_float4(0.f, 0.f, 0.f, 0.f);
        float vv[4] = {v.x, v.y, v.z, v.w};
        unsigned p1[4], p2[4];
#pragma unroll
        for (int j = 0; j < 4; j++) splitpack(vv[j], p1[j], p2[j]);
        *(uint4*)&A1[row * A2_STRIDE + c4 * 4] = make_uint4(p1[0], p1[1], p1[2], p1[3]);
        *(uint4*)&A2[row * A2_STRIDE + c4 * 4] = make_uint4(p2[0], p2[1], p2[2], p2[3]);
    }
    // load B (pre-packed W2): 256x32 u32
#pragma unroll
    for (int i = 0; i < 8; i++) {
        int idx = t + 256 * i;                  // uint4 index, 2048 total
        int row = idx >> 3, c4 = idx & 7;
        uint4 v = *((const uint4*)g_wpk2 + idx);
        *(uint4*)&B[row * B2_STRIDE + c4 * 4] = v;
    }
    __syncthreads();

    const int warp = t >> 5, lane = t & 31;
    const int wm = warp >> 2, wn = warp & 3;
    const int g = lane >> 2, tr = lane & 3;

    float c[2][4] = {};
#pragma unroll 1
    for (int ks = 0; ks < 32; ks++) {
        int kb = ks * 8;
        int col = wn * 8 + g;
        unsigned b0 = B[(kb + tr) * B2_STRIDE + col];
        unsigned b1 = B[(kb + 4 + tr) * B2_STRIDE + col];
#pragma unroll
        for (int pass = 0; pass < 2; pass++) {
            const unsigned* Ap = pass ? A2 : A1;
#pragma unroll
            for (int mt = 0; mt < 2; mt++) {
                int rb = wm * 32 + mt * 16;
                unsigned a0 = Ap[(rb + g) * A2_STRIDE + kb + tr];
                unsigned a1 = Ap[(rb + 8 + g) * A2_STRIDE + kb + tr];
                unsigned a2 = Ap[(rb + g) * A2_STRIDE + kb + 4 + tr];
                unsigned a3 = Ap[(rb + 8 + g) * A2_STRIDE + kb + 4 + tr];
                mma16816(c[mt], a0, a1, a2, a3, b0, b1);
            }
        }
    }

#pragma unroll
    for (int mt = 0; mt < 2; mt++) {
        int r0 = n0 + wm * 32 + mt * 16 + g;
        int col = wn * 8 + tr * 2;
        if (r0 < Nn)
            *(float2*)&g_h2[(size_t)r0 * 32 + col] = make_float2(c[mt][0], c[mt][1]);
        if (r0 + 8 < Nn)
            *(float2*)&g_h2[(size_t)(r0 + 8) * 32 + col] = make_float2(c[mt][2], c[mt][3]);
    }
}

// ---------------- layer 2 el/er: warp per node ----------------
__global__ void elr2_kernel(const float* __restrict__ al, const float* __restrict__ ar) {
    const int wid = (blockIdx.x * blockDim.x + threadIdx.x) >> 5;
    const int lane = threadIdx.x & 31;
    if (wid >= Nn) return;
    float h = g_h2[(size_t)wid * 32 + lane];
    float e = wred(h * __ldg(al + lane));
    float r = wred(h * __ldg(ar + lane));
    if (lane == 0) { g_el2[wid] = e; g_er2[wid] = r; }
}

// ---------------- layer 2 aggregation fused with layer-3 projection ----------
__global__ void __launch_bounds__(256) agg2f_kernel(const float* __restrict__ b2,
                                                    float* __restrict__ emb,
                                                    const float* __restrict__ W3,
                                                    const float* __restrict__ al3,
                                                    const float* __restrict__ ar3) {
    __shared__ float W3s[32 * 64];
    __shared__ float al3s[64], ar3s[64];
    const int t = threadIdx.x;
#pragma unroll
    for (int i = 0; i < 8; i++) W3s[t + 256 * i] = __ldg(W3 + t + 256 * i);
    if (t < 64) { al3s[t] = __ldg(al3 + t); ar3s[t] = __ldg(ar3 + t); }
    __syncthreads();

    const int wid = (blockIdx.x * blockDim.x + t) >> 5;
    const int lane = t & 31;
    if (wid >= Nn) return;
    const int d = wid;
    const int rs = g_rowstart[d], re = g_rowstart[d + 1];
    const float erd = g_er2[d];
    float acc = 0.f, s = 0.f;
    for (int e = rs; e < re; e++) {
        int src = g_esrc[e];
        float ee = __expf(lrelu(g_el2[src] + erd));
        s += ee;
        acc = fmaf(ee, g_h2[(size_t)src * 32 + lane], acc);
    }
    float v = (s > 0.f) ? acc / s : 0.f;
    v += __ldg(b2 + lane);
    emb[(size_t)d * 32 + lane] = v;

    // layer-3 projection: h3[c] = sum_k v[k] * W3[k,c], c = lane, lane+32
    float a0 = 0.f, a1 = 0.f;
#pragma unroll
    for (int k = 0; k < 32; k++) {
        float ek = __shfl_sync(0xffffffffu, v, k);
        a0 = fmaf(ek, W3s[k * 64 + lane], a0);
        a1 = fmaf(ek, W3s[k * 64 + 32 + lane], a1);
    }
    g_h3[(size_t)d * 64 + lane]      = a0;
    g_h3[(size_t)d * 64 + 32 + lane] = a1;
    float e3 = wred(a0 * al3s[lane] + a1 * al3s[32 + lane]);
    float r3 = wred(a0 * ar3s[lane] + a1 * ar3s[32 + lane]);
    if (lane == 0) { g_el3[d] = e3; g_er3[d] = r3; }
}

// ---------------- layer 3 aggregation ----------------
__global__ void agg3_kernel(const float* __restrict__ b3, float* __restrict__ out) {
    const int wid = (blockIdx.x * blockDim.x + threadIdx.x) >> 5;
    const int lane = threadIdx.x & 31;
    if (wid >= Nn) return;
    const int d = wid;
    const int rs = g_rowstart[d], re = g_rowstart[d + 1];
    const float erd = g_er3[d];
    float acc0 = 0.f, acc1 = 0.f, s = 0.f;
    for (int e = rs; e < re; e++) {
        int src = g_esrc[e];
        float ee = __expf(lrelu(g_el3[src] + erd));
        s += ee;
        const float* hp = g_h3 + (size_t)src * 64;
        acc0 = fmaf(ee, hp[lane], acc0);
        acc1 = fmaf(ee, hp[32 + lane], acc1);
    }
    float inv = (s > 0.f) ? (1.f / s) : 0.f;
    out[(size_t)d * 64 + lane]      = acc0 * inv + __ldg(b3 + lane);
    out[(size_t)d * 64 + 32 + lane] = acc1 * inv + __ldg(b3 + 32 + lane);
}

// ---------------- launch ----------------
extern "C" void kernel_launch(void* const* d_in, const int* in_sizes, int n_in,
                              void* d_out, int out_size) {
    const float* features = (const float*)d_in[0];
    const int*   src      = (const int*)d_in[1];
    const int*   dst      = (const int*)d_in[2];
    const float* W1  = (const float*)d_in[3];
    const float* al1 = (const float*)d_in[4];
    const float* ar1 = (const float*)d_in[5];
    const float* b1  = (const float*)d_in[6];
    const float* W2  = (const float*)d_in[7];
    const float* al2 = (const float*)d_in[8];
    const float* ar2 = (const float*)d_in[9];
    const float* b2  = (const float*)d_in[10];
    const float* W3  = (const float*)d_in[11];
    const float* al3 = (const float*)d_in[12];
    const float* ar3 = (const float*)d_in[13];
    const float* b3  = (const float*)d_in[14];

    float* out = (float*)d_out;                 // h: [N,64] first
    float* emb = out + (size_t)Nn * 64;         // embedding: [N,32] second

    static bool attr_set = false;
    if (!attr_set) {
        cudaFuncSetAttribute(gemm1m_kernel, cudaFuncAttributeMaxDynamicSharedMemorySize, G1_SMEM);
        cudaFuncSetAttribute(gemm2m_kernel, cudaFuncAttributeMaxDynamicSharedMemorySize, G2_SMEM);
        attr_set = true;
    }

    // CSR build
    zero_kernel<<<(Nn + 255) / 256, 256>>>();
    count_kernel<<<(Ne + 255) / 256, 256>>>(dst);
    scan_kernel<<<1, 1024>>>();
    scatter_kernel<<<(Ne + 255) / 256, 256>>>(src, dst);

    // weight packing
    wpack_kernel<<<128, 256>>>(W1);
    wpack2_kernel<<<32, 256>>>(W2);

    // layer 1
    gemm1m_kernel<<<(Nn + 63) / 64, 256, G1_SMEM>>>(features, al1, ar1);
    agg1_kernel<<<Nn / 8, 256>>>(b1);
    // layer 2 (+ fused layer-3 projection)
    gemm2m_kernel<<<(Nn + 63) / 64, 256, G2_SMEM>>>();
    elr2_kernel<<<Nn / 8, 256>>>(al2, ar2);
    agg2f_kernel<<<Nn / 8, 256>>>(b2, emb, W3, al3, ar3);
    // layer 3
    agg3_kernel<<<Nn / 8, 256>>>(b3, out);
}

// round 5
// speedup vs baseline: 1.2644x; 1.2056x over previous
#include <cuda_runtime.h>
#include <cuda_fp16.h>
#include <cuda_bf16.h>

#define Nn 50000
#define Ne 800000
// IN=128, H1=8, HID=32, OUT=64

// ---------------- device scratch ----------------
__device__ __half g_h1h[(size_t)Nn * 256];  // layer1 features fp16 [N,8,32]
__device__ float g_x1[(size_t)Nn * 256];    // layer1 output (relu) = layer2 input
__device__ float g_el1[Nn * 8], g_er1[Nn * 8];
__device__ __half g_h2h[(size_t)Nn * 32];
__device__ float g_el2[Nn], g_er2[Nn];
__device__ __half g_h3h[(size_t)Nn * 64];
__device__ float g_el3[Nn], g_er3[Nn];

__device__ int g_deg[Nn];
__device__ int g_fill[Nn];
__device__ int g_rowstart[Nn + 1];
__device__ int g_esrc[Ne];

__device__ unsigned g_wpk[128 * 256];      // W1 packed bf16 hi/lo
__device__ unsigned g_wpk2[256 * 32];      // W2 packed bf16 hi/lo

// ---------------- helpers ----------------
__device__ __forceinline__ float wred(float v) {
#pragma unroll
    for (int o = 16; o > 0; o >>= 1) v += __shfl_xor_sync(0xffffffffu, v, o);
    return v;
}

__device__ __forceinline__ float lrelu(float x) {
    return x > 0.f ? x : 0.2f * x;
}

__device__ __forceinline__ void mma16816(float c[4], unsigned a0, unsigned a1,
                                         unsigned a2, unsigned a3,
                                         unsigned b0, unsigned b1) {
    asm volatile(
        "mma.sync.aligned.m16n8k16.row.col.f32.bf16.bf16.f32 "
        "{%0,%1,%2,%3}, {%4,%5,%6,%7}, {%8,%9}, {%0,%1,%2,%3};\n"
        : "+f"(c[0]), "+f"(c[1]), "+f"(c[2]), "+f"(c[3])
        : "r"(a0), "r"(a1), "r"(a2), "r"(a3), "r"(b0), "r"(b1));
}

__device__ __forceinline__ void splitpack(float v, unsigned& dup_hi, unsigned& dup_lo) {
    __nv_bfloat16 h = __float2bfloat16(v);
    float hf = __bfloat162float(h);
    __nv_bfloat16 l = __float2bfloat16(v - hf);
    unsigned hb = __bfloat16_as_ushort(h);
    unsigned lb = __bfloat16_as_ushort(l);
    dup_hi = hb | (hb << 16);
    dup_lo = lb | (lb << 16);
}

// ---------------- CSR build ----------------
__global__ void zero_kernel() {
    int i = blockIdx.x * blockDim.x + threadIdx.x;
    if (i < Nn) { g_deg[i] = 0; g_fill[i] = 0; }
}

__global__ void count_kernel(const int* __restrict__ dst) {
    int e = blockIdx.x * blockDim.x + threadIdx.x;
    if (e < Ne) atomicAdd(&g_deg[dst[e]], 1);
}

__global__ void scan_kernel() {
    __shared__ int warpsum[32];
    const int t = threadIdx.x;            // 1024
    const int lane = t & 31, wid = t >> 5;
    const int CH = (Nn + 1023) / 1024;
    const int base = t * CH;
    int sum = 0;
#pragma unroll 1
    for (int i = 0; i < CH; i++) {
        int idx = base + i;
        if (idx < Nn) sum += g_deg[idx];
    }
    int v = sum;
#pragma unroll
    for (int o = 1; o < 32; o <<= 1) {
        int u = __shfl_up_sync(0xffffffffu, v, o);
        if (lane >= o) v += u;
    }
    if (lane == 31) warpsum[wid] = v;
    __syncthreads();
    if (wid == 0) {
        int w = warpsum[lane];
        int vv = w;
#pragma unroll
        for (int o = 1; o < 32; o <<= 1) {
            int u = __shfl_up_sync(0xffffffffu, vv, o);
            if (lane >= o) vv += u;
        }
        warpsum[lane] = vv;
    }
    __syncthreads();
    int excl = v - sum + (wid > 0 ? warpsum[wid - 1] : 0);
    int run = excl;
#pragma unroll 1
    for (int i = 0; i < CH; i++) {
        int idx = base + i;
        if (idx < Nn) { g_rowstart[idx] = run; run += g_deg[idx]; }
    }
    if (t == 1023) g_rowstart[Nn] = run;
}

__global__ void scatter_kernel(const int* __restrict__ src, const int* __restrict__ dst) {
    int e = blockIdx.x * blockDim.x + threadIdx.x;
    if (e >= Ne) return;
    int d = dst[e];
    int pos = g_rowstart[d] + atomicAdd(&g_fill[d], 1);
    g_esrc[pos] = src[e];
}

// ---------------- W packing (bf16 hi/lo), both weights in one launch --------
__global__ void wpack_kernel(const float* __restrict__ W1, const float* __restrict__ W2) {
    int i = blockIdx.x * blockDim.x + threadIdx.x;   // 40960
    float w;
    if (i < 32768) w = W1[i];
    else           w = W2[i - 32768];
    __nv_bfloat16 h = __float2bfloat16(w);
    float hf = __bfloat162float(h);
    __nv_bfloat16 l = __float2bfloat16(w - hf);
    unsigned p = (unsigned)__bfloat16_as_ushort(h) | ((unsigned)__bfloat16_as_ushort(l) << 16);
    if (i < 32768) g_wpk[i] = p;
    else           g_wpk2[i - 32768] = p;
}

// ---------------- layer 1 GEMM (TC, bf16 split) + el/er epilogue ------------
#define A_STRIDE 132
#define B_STRIDE 264
#define G1_SMEM ((2 * 64 * A_STRIDE + 128 * B_STRIDE) * 4)

__global__ void __launch_bounds__(256) gemm1m_kernel(const float* __restrict__ X,
                                                     const float* __restrict__ al,
                                                     const float* __restrict__ ar) {
    extern __shared__ unsigned smem[];
    unsigned* A1 = smem;
    unsigned* A2 = smem + 64 * A_STRIDE;
    unsigned* B  = smem + 2 * 64 * A_STRIDE;

    const int t = threadIdx.x;
    const int n0 = blockIdx.x * 64;

#pragma unroll
    for (int i = 0; i < 8; i++) {
        int idx = t + 256 * i;
        int row = idx >> 5, c4 = idx & 31;
        int grow = n0 + row;
        float4 v = (grow < Nn) ? __ldg((const float4*)(X + (size_t)grow * 128) + c4)
                               : make_float4(0.f, 0.f, 0.f, 0.f);
        float vv[4] = {v.x, v.y, v.z, v.w};
        unsigned p1[4], p2[4];
#pragma unroll
        for (int j = 0; j < 4; j++) splitpack(vv[j], p1[j], p2[j]);
        *(uint4*)&A1[row * A_STRIDE + c4 * 4] = make_uint4(p1[0], p1[1], p1[2], p1[3]);
        *(uint4*)&A2[row * A_STRIDE + c4 * 4] = make_uint4(p2[0], p2[1], p2[2], p2[3]);
    }
#pragma unroll
    for (int i = 0; i < 32; i++) {
        int idx = t + 256 * i;
        int row = idx >> 6, c4 = idx & 63;
        uint4 v = *((const uint4*)g_wpk + idx);
        *(uint4*)&B[row * B_STRIDE + c4 * 4] = v;
    }
    __syncthreads();

    const int warp = t >> 5, lane = t & 31;
    const int wm = warp >> 2, wn = warp & 3;
    const int g = lane >> 2, tr = lane & 3;

    float c[2][8][4] = {};
#pragma unroll 1
    for (int ks = 0; ks < 16; ks++) {
        int kb = ks * 8;
        unsigned b0[8], b1[8];
#pragma unroll
        for (int nt = 0; nt < 8; nt++) {
            int col = wn * 64 + nt * 8 + g;
            b0[nt] = B[(kb + tr) * B_STRIDE + col];
            b1[nt] = B[(kb + 4 + tr) * B_STRIDE + col];
        }
#pragma unroll
        for (int pass = 0; pass < 2; pass++) {
            const unsigned* Ap = pass ? A2 : A1;
#pragma unroll
            for (int mt = 0; mt < 2; mt++) {
                int rb = wm * 32 + mt * 16;
                unsigned a0 = Ap[(rb + g) * A_STRIDE + kb + tr];
                unsigned a1 = Ap[(rb + 8 + g) * A_STRIDE + kb + tr];
                unsigned a2 = Ap[(rb + g) * A_STRIDE + kb + 4 + tr];
                unsigned a3 = Ap[(rb + 8 + g) * A_STRIDE + kb + 4 + tr];
#pragma unroll
                for (int nt = 0; nt < 8; nt++)
                    mma16816(c[mt][nt], a0, a1, a2, a3, b0[nt], b1[nt]);
            }
        }
    }

    float alv[8][2], arv[8][2];
#pragma unroll
    for (int nt = 0; nt < 8; nt++) {
        int col = wn * 64 + nt * 8 + tr * 2;
        alv[nt][0] = __ldg(al + col);  alv[nt][1] = __ldg(al + col + 1);
        arv[nt][0] = __ldg(ar + col);  arv[nt][1] = __ldg(ar + col + 1);
    }

#pragma unroll
    for (int mt = 0; mt < 2; mt++) {
#pragma unroll
        for (int half = 0; half < 2; half++) {
            int r = n0 + wm * 32 + mt * 16 + g + 8 * half;
            float pe0 = 0.f, pe1 = 0.f, pr0 = 0.f, pr1 = 0.f;
#pragma unroll
            for (int nt = 0; nt < 8; nt++) {
                float c0 = c[mt][nt][2 * half], c1 = c[mt][nt][2 * half + 1];
                int col = wn * 64 + nt * 8 + tr * 2;
                if (r < Nn)
                    *(__half2*)&g_h1h[(size_t)r * 256 + col] = __floats2half2_rn(c0, c1);
                float pe = c0 * alv[nt][0] + c1 * alv[nt][1];
                float pr = c0 * arv[nt][0] + c1 * arv[nt][1];
                if (nt < 4) { pe0 += pe; pr0 += pr; }
                else        { pe1 += pe; pr1 += pr; }
            }
            pe0 += __shfl_xor_sync(0xffffffffu, pe0, 1);
            pe0 += __shfl_xor_sync(0xffffffffu, pe0, 2);
            pe1 += __shfl_xor_sync(0xffffffffu, pe1, 1);
            pe1 += __shfl_xor_sync(0xffffffffu, pe1, 2);
            pr0 += __shfl_xor_sync(0xffffffffu, pr0, 1);
            pr0 += __shfl_xor_sync(0xffffffffu, pr0, 2);
            pr1 += __shfl_xor_sync(0xffffffffu, pr1, 1);
            pr1 += __shfl_xor_sync(0xffffffffu, pr1, 2);
            if (tr == 0 && r < Nn) {
                g_el1[r * 8 + 2 * wn]     = pe0;
                g_el1[r * 8 + 2 * wn + 1] = pe1;
                g_er1[r * 8 + 2 * wn]     = pr0;
                g_er1[r * 8 + 2 * wn + 1] = pr1;
            }
        }
    }
}

// ---------------- layer 1 aggregation: warp/dst, 4x unrolled gather --------
__global__ void agg1_kernel(const float* __restrict__ b1) {
    const int wid = (blockIdx.x * blockDim.x + threadIdx.x) >> 5;
    const int lane = threadIdx.x & 31;
    const int d = wid;
    const int rs = g_rowstart[d], re = g_rowstart[d + 1];
    const float erh = (lane < 8) ? g_er1[d * 8 + lane] : 0.f;
    const int h0 = lane >> 4;  // lane owns cols {64q+2lane,+1}; head(q)=2q+h0
    float2 acc[4] = {{0, 0}, {0, 0}, {0, 0}, {0, 0}};
    float s = 0.f;
    int e = rs;
    for (; e + 4 <= re; e += 4) {
        int s0 = g_esrc[e], s1 = g_esrc[e + 1], s2 = g_esrc[e + 2], s3 = g_esrc[e + 3];
        float l0 = 0.f, l1 = 0.f, l2 = 0.f, l3 = 0.f;
        if (lane < 8) {
            l0 = g_el1[s0 * 8 + lane]; l1 = g_el1[s1 * 8 + lane];
            l2 = g_el1[s2 * 8 + lane]; l3 = g_el1[s3 * 8 + lane];
        }
        const __half2* p0 = (const __half2*)(g_h1h + (size_t)s0 * 256);
        const __half2* p1 = (const __half2*)(g_h1h + (size_t)s1 * 256);
        const __half2* p2 = (const __half2*)(g_h1h + (size_t)s2 * 256);
        const __half2* p3 = (const __half2*)(g_h1h + (size_t)s3 * 256);
        __half2 v0[4], v1[4], v2[4], v3[4];
#pragma unroll
        for (int q = 0; q < 4; q++) v0[q] = p0[q * 32 + lane];
#pragma unroll
        for (int q = 0; q < 4; q++) v1[q] = p1[q * 32 + lane];
#pragma unroll
        for (int q = 0; q < 4; q++) v2[q] = p2[q * 32 + lane];
#pragma unroll
        for (int q = 0; q < 4; q++) v3[q] = p3[q * 32 + lane];
        float e0 = 0.f, e1 = 0.f, e2 = 0.f, e3 = 0.f;
        if (lane < 8) {
            e0 = __expf(lrelu(l0 + erh)); e1 = __expf(lrelu(l1 + erh));
            e2 = __expf(lrelu(l2 + erh)); e3 = __expf(lrelu(l3 + erh));
            s += (e0 + e1) + (e2 + e3);
        }
#pragma unroll
        for (int q = 0; q < 4; q++) {
            int hsel = 2 * q + h0;
            float w0 = __shfl_sync(0xffffffffu, e0, hsel);
            float w1 = __shfl_sync(0xffffffffu, e1, hsel);
            float w2 = __shfl_sync(0xffffffffu, e2, hsel);
            float w3 = __shfl_sync(0xffffffffu, e3, hsel);
            float2 f0 = __half22float2(v0[q]), f1 = __half22float2(v1[q]);
            float2 f2 = __half22float2(v2[q]), f3 = __half22float2(v3[q]);
            acc[q].x = fmaf(w0, f0.x, fmaf(w1, f1.x, fmaf(w2, f2.x, fmaf(w3, f3.x, acc[q].x))));
            acc[q].y = fmaf(w0, f0.y, fmaf(w1, f1.y, fmaf(w2, f2.y, fmaf(w3, f3.y, acc[q].y))));
        }
    }
    for (; e < re; e++) {
        int src = g_esrc[e];
        float ee = 0.f;
        if (lane < 8) {
            ee = __expf(lrelu(g_el1[src * 8 + lane] + erh));
            s += ee;
        }
        const __half2* hp = (const __half2*)(g_h1h + (size_t)src * 256);
#pragma unroll
        for (int q = 0; q < 4; q++) {
            float eh = __shfl_sync(0xffffffffu, ee, 2 * q + h0);
            float2 f = __half22float2(hp[q * 32 + lane]);
            acc[q].x = fmaf(eh, f.x, acc[q].x);
            acc[q].y = fmaf(eh, f.y, acc[q].y);
        }
    }
#pragma unroll
    for (int q = 0; q < 4; q++) {
        float sh = __shfl_sync(0xffffffffu, s, 2 * q + h0);
        float inv = (sh > 0.f) ? (1.f / sh) : 0.f;
        int col = 64 * q + 2 * lane;
        float vx = fmaxf(acc[q].x * inv + __ldg(b1 + col), 0.f);
        float vy = fmaxf(acc[q].y * inv + __ldg(b1 + col + 1), 0.f);
        *(float2*)&g_x1[(size_t)d * 256 + col] = make_float2(vx, vy);
    }
}

// ---------------- layer 2 GEMM (TC, bf16 split) + fused el2/er2 ------------
#define A2_STRIDE 260
#define B2_STRIDE 40
#define G2_SMEM ((2 * 64 * A2_STRIDE + 256 * B2_STRIDE) * 4)

__global__ void __launch_bounds__(256) gemm2m_kernel(const float* __restrict__ al,
                                                     const float* __restrict__ ar) {
    extern __shared__ unsigned smem[];
    unsigned* A1 = smem;
    unsigned* A2 = smem + 64 * A2_STRIDE;
    unsigned* B  = smem + 2 * 64 * A2_STRIDE;

    const int t = threadIdx.x;
    const int n0 = blockIdx.x * 64;

#pragma unroll
    for (int i = 0; i < 16; i++) {
        int idx = t + 256 * i;
        int row = idx >> 6, c4 = idx & 63;
        int grow = n0 + row;
        float4 v = (grow < Nn) ? *((const float4*)(g_x1 + (size_t)grow * 256) + c4)
                               : make_float4(0.f, 0.f, 0.f, 0.f);
        float vv[4] = {v.x, v.y, v.z, v.w};
        unsigned p1[4], p2[4];
#pragma unroll
        for (int j = 0; j < 4; j++) splitpack(vv[j], p1[j], p2[j]);
        *(uint4*)&A1[row * A2_STRIDE + c4 * 4] = make_uint4(p1[0], p1[1], p1[2], p1[3]);
        *(uint4*)&A2[row * A2_STRIDE + c4 * 4] = make_uint4(p2[0], p2[1], p2[2], p2[3]);
    }
#pragma unroll
    for (int i = 0; i < 8; i++) {
        int idx = t + 256 * i;
        int row = idx >> 3, c4 = idx & 7;
        uint4 v = *((const uint4*)g_wpk2 + idx);
        *(uint4*)&B[row * B2_STRIDE + c4 * 4] = v;
    }
    __syncthreads();

    const int warp = t >> 5, lane = t & 31;
    const int wm = warp >> 2, wn = warp & 3;
    const int g = lane >> 2, tr = lane & 3;

    float c[2][4] = {};
#pragma unroll 1
    for (int ks = 0; ks < 32; ks++) {
        int kb = ks * 8;
        int col = wn * 8 + g;
        unsigned b0 = B[(kb + tr) * B2_STRIDE + col];
        unsigned b1 = B[(kb + 4 + tr) * B2_STRIDE + col];
#pragma unroll
        for (int pass = 0; pass < 2; pass++) {
            const unsigned* Ap = pass ? A2 : A1;
#pragma unroll
            for (int mt = 0; mt < 2; mt++) {
                int rb = wm * 32 + mt * 16;
                unsigned a0 = Ap[(rb + g) * A2_STRIDE + kb + tr];
                unsigned a1 = Ap[(rb + 8 + g) * A2_STRIDE + kb + tr];
                unsigned a2 = Ap[(rb + g) * A2_STRIDE + kb + 4 + tr];
                unsigned a3 = Ap[(rb + 8 + g) * A2_STRIDE + kb + 4 + tr];
                mma16816(c[mt], a0, a1, a2, a3, b0, b1);
            }
        }
    }
    __syncthreads();   // smem reuse for epilogue reduction

    float* epi_e = (float*)smem;          // [64][4]
    float* epi_r = (float*)smem + 256;    // [64][4]

    const int col = wn * 8 + tr * 2;
    const float a0v = __ldg(al + col), a1v = __ldg(al + col + 1);
    const float r0v = __ldg(ar + col), r1v = __ldg(ar + col + 1);

#pragma unroll
    for (int mt = 0; mt < 2; mt++) {
#pragma unroll
        for (int half = 0; half < 2; half++) {
            int lrow = wm * 32 + mt * 16 + g + 8 * half;
            int r = n0 + lrow;
            float c0 = c[mt][2 * half], c1 = c[mt][2 * half + 1];
            if (r < Nn)
                *(__half2*)&g_h2h[(size_t)r * 32 + col] = __floats2half2_rn(c0, c1);
            float pe = c0 * a0v + c1 * a1v;
            float pr = c0 * r0v + c1 * r1v;
            pe += __shfl_xor_sync(0xffffffffu, pe, 1);
            pe += __shfl_xor_sync(0xffffffffu, pe, 2);
            pr += __shfl_xor_sync(0xffffffffu, pr, 1);
            pr += __shfl_xor_sync(0xffffffffu, pr, 2);
            if (tr == 0) {
                epi_e[lrow * 4 + wn] = pe;
                epi_r[lrow * 4 + wn] = pr;
            }
        }
    }
    __syncthreads();
    if (t < 64) {
        int n = n0 + t;
        if (n < Nn) {
            g_el2[n] = epi_e[t * 4] + epi_e[t * 4 + 1] + epi_e[t * 4 + 2] + epi_e[t * 4 + 3];
            g_er2[n] = epi_r[t * 4] + epi_r[t * 4 + 1] + epi_r[t * 4 + 2] + epi_r[t * 4 + 3];
        }
    }
}

// ---------------- layer 2 aggregation + fused layer-3 projection -----------
__global__ void __launch_bounds__(256) agg2f_kernel(const float* __restrict__ b2,
                                                    float* __restrict__ emb,
                                                    const float* __restrict__ W3,
                                                    const float* __restrict__ al3,
                                                    const float* __restrict__ ar3) {
    __shared__ float W3s[32 * 64];
    __shared__ float al3s[64], ar3s[64];
    const int t = threadIdx.x;
#pragma unroll
    for (int i = 0; i < 8; i++) W3s[t + 256 * i] = __ldg(W3 + t + 256 * i);
    if (t < 64) { al3s[t] = __ldg(al3 + t); ar3s[t] = __ldg(ar3 + t); }
    __syncthreads();

    const int wid = (blockIdx.x * blockDim.x + t) >> 5;
    const int lane = t & 31;
    const int d = wid;
    const int rs = g_rowstart[d], re = g_rowstart[d + 1];
    const float erd = g_er2[d];
    float acc = 0.f, s = 0.f;
    int e = rs;
    for (; e + 4 <= re; e += 4) {
        int s0 = g_esrc[e], s1 = g_esrc[e + 1], s2 = g_esrc[e + 2], s3 = g_esrc[e + 3];
        float l0 = g_el2[s0], l1 = g_el2[s1], l2 = g_el2[s2], l3 = g_el2[s3];
        float h0 = __half2float(g_h2h[(size_t)s0 * 32 + lane]);
        float h1 = __half2float(g_h2h[(size_t)s1 * 32 + lane]);
        float h2 = __half2float(g_h2h[(size_t)s2 * 32 + lane]);
        float h3 = __half2float(g_h2h[(size_t)s3 * 32 + lane]);
        float e0 = __expf(lrelu(l0 + erd)), e1 = __expf(lrelu(l1 + erd));
        float e2 = __expf(lrelu(l2 + erd)), e3 = __expf(lrelu(l3 + erd));
        s += (e0 + e1) + (e2 + e3);
        acc = fmaf(e0, h0, fmaf(e1, h1, fmaf(e2, h2, fmaf(e3, h3, acc))));
    }
    for (; e < re; e++) {
        int src = g_esrc[e];
        float ee = __expf(lrelu(g_el2[src] + erd));
        s += ee;
        acc = fmaf(ee, __half2float(g_h2h[(size_t)src * 32 + lane]), acc);
    }
    float v = (s > 0.f) ? acc / s : 0.f;
    v += __ldg(b2 + lane);
    emb[(size_t)d * 32 + lane] = v;

    // layer-3 projection
    float a0 = 0.f, a1 = 0.f;
#pragma unroll
    for (int k = 0; k < 32; k++) {
        float ek = __shfl_sync(0xffffffffu, v, k);
        a0 = fmaf(ek, W3s[k * 64 + lane], a0);
        a1 = fmaf(ek, W3s[k * 64 + 32 + lane], a1);
    }
    g_h3h[(size_t)d * 64 + lane]      = __float2half(a0);
    g_h3h[(size_t)d * 64 + 32 + lane] = __float2half(a1);
    float e3 = wred(a0 * al3s[lane] + a1 * al3s[32 + lane]);
    float r3 = wred(a0 * ar3s[lane] + a1 * ar3s[32 + lane]);
    if (lane == 0) { g_el3[d] = e3; g_er3[d] = r3; }
}

// ---------------- layer 3 aggregation: 4x unrolled, half2 gathers ----------
__global__ void agg3_kernel(const float* __restrict__ b3, float* __restrict__ out) {
    const int wid = (blockIdx.x * blockDim.x + threadIdx.x) >> 5;
    const int lane = threadIdx.x & 31;
    const int d = wid;
    const int rs = g_rowstart[d], re = g_rowstart[d + 1];
    const float erd = g_er3[d];
    float ax = 0.f, ay = 0.f, s = 0.f;
    int e = rs;
    for (; e + 4 <= re; e += 4) {
        int s0 = g_esrc[e], s1 = g_esrc[e + 1], s2 = g_esrc[e + 2], s3 = g_esrc[e + 3];
        float l0 = g_el3[s0], l1 = g_el3[s1], l2 = g_el3[s2], l3 = g_el3[s3];
        __half2 v0 = *((const __half2*)(g_h3h + (size_t)s0 * 64) + lane);
        __half2 v1 = *((const __half2*)(g_h3h + (size_t)s1 * 64) + lane);
        __half2 v2 = *((const __half2*)(g_h3h + (size_t)s2 * 64) + lane);
        __half2 v3 = *((const __half2*)(g_h3h + (size_t)s3 * 64) + lane);
        float e0 = __expf(lrelu(l0 + erd)), e1 = __expf(lrelu(l1 + erd));
        float e2 = __expf(lrelu(l2 + erd)), e3 = __expf(lrelu(l3 + erd));
        s += (e0 + e1) + (e2 + e3);
        float2 f0 = __half22float2(v0), f1 = __half22float2(v1);
        float2 f2 = __half22float2(v2), f3 = __half22float2(v3);
        ax = fmaf(e0, f0.x, fmaf(e1, f1.x, fmaf(e2, f2.x, fmaf(e3, f3.x, ax))));
        ay = fmaf(e0, f0.y, fmaf(e1, f1.y, fmaf(e2, f2.y, fmaf(e3, f3.y, ay))));
    }
    for (; e < re; e++) {
        int src = g_esrc[e];
        float ee = __expf(lrelu(g_el3[src] + erd));
        s += ee;
        float2 f = __half22float2(*((const __half2*)(g_h3h + (size_t)src * 64) + lane));
        ax = fmaf(ee, f.x, ax);
        ay = fmaf(ee, f.y, ay);
    }
    float inv = (s > 0.f) ? (1.f / s) : 0.f;
    int col = 2 * lane;
    float ox = ax * inv + __ldg(b3 + col);
    float oy = ay * inv + __ldg(b3 + col + 1);
    *(float2*)&out[(size_t)d * 64 + col] = make_float2(ox, oy);
}

// ---------------- launch ----------------
extern "C" void kernel_launch(void* const* d_in, const int* in_sizes, int n_in,
                              void* d_out, int out_size) {
    const float* features = (const float*)d_in[0];
    const int*   src      = (const int*)d_in[1];
    const int*   dst      = (const int*)d_in[2];
    const float* W1  = (const float*)d_in[3];
    const float* al1 = (const float*)d_in[4];
    const float* ar1 = (const float*)d_in[5];
    const float* b1  = (const float*)d_in[6];
    const float* W2  = (const float*)d_in[7];
    const float* al2 = (const float*)d_in[8];
    const float* ar2 = (const float*)d_in[9];
    const float* b2  = (const float*)d_in[10];
    const float* W3  = (const float*)d_in[11];
    const float* al3 = (const float*)d_in[12];
    const float* ar3 = (const float*)d_in[13];
    const float* b3  = (const float*)d_in[14];

    float* out = (float*)d_out;                 // h: [N,64]
    float* emb = out + (size_t)Nn * 64;         // embedding: [N,32]

    static bool attr_set = false;
    if (!attr_set) {
        cudaFuncSetAttribute(gemm1m_kernel, cudaFuncAttributeMaxDynamicSharedMemorySize, G1_SMEM);
        cudaFuncSetAttribute(gemm2m_kernel, cudaFuncAttributeMaxDynamicSharedMemorySize, G2_SMEM);
        attr_set = true;
    }

    // CSR build
    zero_kernel<<<(Nn + 255) / 256, 256>>>();
    count_kernel<<<(Ne + 255) / 256, 256>>>(dst);
    scan_kernel<<<1, 1024>>>();
    scatter_kernel<<<(Ne + 255) / 256, 256>>>(src, dst);

    // weight packing
    wpack_kernel<<<160, 256>>>(W1, W2);

    // layer 1
    gemm1m_kernel<<<(Nn + 63) / 64, 256, G1_SMEM>>>(features, al1, ar1);
    agg1_kernel<<<Nn / 8, 256>>>(b1);
    // layer 2 (+ fused el/er and layer-3 projection)
    gemm2m_kernel<<<(Nn + 63) / 64, 256, G2_SMEM>>>(al2, ar2);
    agg2f_kernel<<<Nn / 8, 256>>>(b2, emb, W3, al3, ar3);
    // layer 3
    agg3_kernel<<<Nn / 8, 256>>>(b3, out);
}

// round 6
// speedup vs baseline: 1.2912x; 1.0212x over previous
#include <cuda_runtime.h>
#include <cuda_fp16.h>
#include <cuda_bf16.h>

#define Nn 50000
#define Ne 800000
// IN=128, H1=8, HID=32, OUT=64

// ---------------- device scratch ----------------
__device__ __half g_h1h[(size_t)Nn * 256];  // layer1 features fp16 [N,8,32]
__device__ float g_x1[(size_t)Nn * 256];    // layer1 output (relu) = layer2 input
__device__ float g_el1[Nn * 8], g_er1[Nn * 8];
__device__ __half g_h2h[(size_t)Nn * 32];
__device__ float g_el2[Nn], g_er2[Nn];
__device__ __half g_h3h[(size_t)Nn * 64];
__device__ float g_el3[Nn], g_er3[Nn];

__device__ int g_deg[Nn];
__device__ int g_fill[Nn];
__device__ int g_rowstart[Nn + 1];
__device__ int g_esrc[Ne];

__device__ unsigned g_wpk[128 * 256];      // W1 packed bf16 hi/lo
__device__ unsigned g_wpk2[256 * 32];      // W2 packed bf16 hi/lo

// ---------------- helpers ----------------
__device__ __forceinline__ float wred(float v) {
#pragma unroll
    for (int o = 16; o > 0; o >>= 1) v += __shfl_xor_sync(0xffffffffu, v, o);
    return v;
}

__device__ __forceinline__ float lrelu(float x) {
    return x > 0.f ? x : 0.2f * x;
}

__device__ __forceinline__ void mma16816(float c[4], unsigned a0, unsigned a1,
                                         unsigned a2, unsigned a3,
                                         unsigned b0, unsigned b1) {
    asm volatile(
        "mma.sync.aligned.m16n8k16.row.col.f32.bf16.bf16.f32 "
        "{%0,%1,%2,%3}, {%4,%5,%6,%7}, {%8,%9}, {%0,%1,%2,%3};\n"
        : "+f"(c[0]), "+f"(c[1]), "+f"(c[2]), "+f"(c[3])
        : "r"(a0), "r"(a1), "r"(a2), "r"(a3), "r"(b0), "r"(b1));
}

__device__ __forceinline__ void splitpack(float v, unsigned& dup_hi, unsigned& dup_lo) {
    __nv_bfloat16 h = __float2bfloat16(v);
    float hf = __bfloat162float(h);
    __nv_bfloat16 l = __float2bfloat16(v - hf);
    unsigned hb = __bfloat16_as_ushort(h);
    unsigned lb = __bfloat16_as_ushort(l);
    dup_hi = hb | (hb << 16);
    dup_lo = lb | (lb << 16);
}

// ---------------- CSR build ----------------
__global__ void zero_kernel() {
    int i = blockIdx.x * blockDim.x + threadIdx.x;
    if (i < Nn) { g_deg[i] = 0; g_fill[i] = 0; }
}

__global__ void count_kernel(const int* __restrict__ dst) {
    int e = blockIdx.x * blockDim.x + threadIdx.x;
    if (e < Ne) atomicAdd(&g_deg[dst[e]], 1);
}

__global__ void scan_kernel() {
    __shared__ int warpsum[32];
    const int t = threadIdx.x;            // 1024
    const int lane = t & 31, wid = t >> 5;
    const int CH = (Nn + 1023) / 1024;
    const int base = t * CH;
    int sum = 0;
#pragma unroll 1
    for (int i = 0; i < CH; i++) {
        int idx = base + i;
        if (idx < Nn) sum += g_deg[idx];
    }
    int v = sum;
#pragma unroll
    for (int o = 1; o < 32; o <<= 1) {
        int u = __shfl_up_sync(0xffffffffu, v, o);
        if (lane >= o) v += u;
    }
    if (lane == 31) warpsum[wid] = v;
    __syncthreads();
    if (wid == 0) {
        int w = warpsum[lane];
        int vv = w;
#pragma unroll
        for (int o = 1; o < 32; o <<= 1) {
            int u = __shfl_up_sync(0xffffffffu, vv, o);
            if (lane >= o) vv += u;
        }
        warpsum[lane] = vv;
    }
    __syncthreads();
    int excl = v - sum + (wid > 0 ? warpsum[wid - 1] : 0);
    int run = excl;
#pragma unroll 1
    for (int i = 0; i < CH; i++) {
        int idx = base + i;
        if (idx < Nn) { g_rowstart[idx] = run; run += g_deg[idx]; }
    }
    if (t == 1023) g_rowstart[Nn] = run;
}

__global__ void scatter_kernel(const int* __restrict__ src, const int* __restrict__ dst) {
    int e = blockIdx.x * blockDim.x + threadIdx.x;
    if (e >= Ne) return;
    int d = dst[e];
    int pos = g_rowstart[d] + atomicAdd(&g_fill[d], 1);
    g_esrc[pos] = src[e];
}

// ---------------- W packing (bf16 hi/lo) ----------------
__global__ void wpack_kernel(const float* __restrict__ W1, const float* __restrict__ W2) {
    int i = blockIdx.x * blockDim.x + threadIdx.x;   // 40960
    float w;
    if (i < 32768) w = W1[i];
    else           w = W2[i - 32768];
    __nv_bfloat16 h = __float2bfloat16(w);
    float hf = __bfloat162float(h);
    __nv_bfloat16 l = __float2bfloat16(w - hf);
    unsigned p = (unsigned)__bfloat16_as_ushort(h) | ((unsigned)__bfloat16_as_ushort(l) << 16);
    if (i < 32768) g_wpk[i] = p;
    else           g_wpk2[i - 32768] = p;
}

// ---------------- layer 1 GEMM (TC, bf16 split) + el/er epilogue ------------
#define A_STRIDE 132
#define B_STRIDE 264
#define G1_SMEM ((2 * 64 * A_STRIDE + 128 * B_STRIDE) * 4)

__global__ void __launch_bounds__(256) gemm1m_kernel(const float* __restrict__ X,
                                                     const float* __restrict__ al,
                                                     const float* __restrict__ ar) {
    extern __shared__ unsigned smem[];
    unsigned* A1 = smem;
    unsigned* A2 = smem + 64 * A_STRIDE;
    unsigned* B  = smem + 2 * 64 * A_STRIDE;

    const int t = threadIdx.x;
    const int n0 = blockIdx.x * 64;

#pragma unroll
    for (int i = 0; i < 8; i++) {
        int idx = t + 256 * i;
        int row = idx >> 5, c4 = idx & 31;
        int grow = n0 + row;
        float4 v = (grow < Nn) ? __ldg((const float4*)(X + (size_t)grow * 128) + c4)
                               : make_float4(0.f, 0.f, 0.f, 0.f);
        float vv[4] = {v.x, v.y, v.z, v.w};
        unsigned p1[4], p2[4];
#pragma unroll
        for (int j = 0; j < 4; j++) splitpack(vv[j], p1[j], p2[j]);
        *(uint4*)&A1[row * A_STRIDE + c4 * 4] = make_uint4(p1[0], p1[1], p1[2], p1[3]);
        *(uint4*)&A2[row * A_STRIDE + c4 * 4] = make_uint4(p2[0], p2[1], p2[2], p2[3]);
    }
#pragma unroll
    for (int i = 0; i < 32; i++) {
        int idx = t + 256 * i;
        int row = idx >> 6, c4 = idx & 63;
        uint4 v = *((const uint4*)g_wpk + idx);
        *(uint4*)&B[row * B_STRIDE + c4 * 4] = v;
    }
    __syncthreads();

    const int warp = t >> 5, lane = t & 31;
    const int wm = warp >> 2, wn = warp & 3;
    const int g = lane >> 2, tr = lane & 3;

    float c[2][8][4] = {};
#pragma unroll 1
    for (int ks = 0; ks < 16; ks++) {
        int kb = ks * 8;
        unsigned b0[8], b1[8];
#pragma unroll
        for (int nt = 0; nt < 8; nt++) {
            int col = wn * 64 + nt * 8 + g;
            b0[nt] = B[(kb + tr) * B_STRIDE + col];
            b1[nt] = B[(kb + 4 + tr) * B_STRIDE + col];
        }
#pragma unroll
        for (int pass = 0; pass < 2; pass++) {
            const unsigned* Ap = pass ? A2 : A1;
#pragma unroll
            for (int mt = 0; mt < 2; mt++) {
                int rb = wm * 32 + mt * 16;
                unsigned a0 = Ap[(rb + g) * A_STRIDE + kb + tr];
                unsigned a1 = Ap[(rb + 8 + g) * A_STRIDE + kb + tr];
                unsigned a2 = Ap[(rb + g) * A_STRIDE + kb + 4 + tr];
                unsigned a3 = Ap[(rb + 8 + g) * A_STRIDE + kb + 4 + tr];
#pragma unroll
                for (int nt = 0; nt < 8; nt++)
                    mma16816(c[mt][nt], a0, a1, a2, a3, b0[nt], b1[nt]);
            }
        }
    }

    float alv[8][2], arv[8][2];
#pragma unroll
    for (int nt = 0; nt < 8; nt++) {
        int col = wn * 64 + nt * 8 + tr * 2;
        alv[nt][0] = __ldg(al + col);  alv[nt][1] = __ldg(al + col + 1);
        arv[nt][0] = __ldg(ar + col);  arv[nt][1] = __ldg(ar + col + 1);
    }

#pragma unroll
    for (int mt = 0; mt < 2; mt++) {
#pragma unroll
        for (int half = 0; half < 2; half++) {
            int r = n0 + wm * 32 + mt * 16 + g + 8 * half;
            float pe0 = 0.f, pe1 = 0.f, pr0 = 0.f, pr1 = 0.f;
#pragma unroll
            for (int nt = 0; nt < 8; nt++) {
                float c0 = c[mt][nt][2 * half], c1 = c[mt][nt][2 * half + 1];
                int col = wn * 64 + nt * 8 + tr * 2;
                if (r < Nn)
                    *(__half2*)&g_h1h[(size_t)r * 256 + col] = __floats2half2_rn(c0, c1);
                float pe = c0 * alv[nt][0] + c1 * alv[nt][1];
                float pr = c0 * arv[nt][0] + c1 * arv[nt][1];
                if (nt < 4) { pe0 += pe; pr0 += pr; }
                else        { pe1 += pe; pr1 += pr; }
            }
            pe0 += __shfl_xor_sync(0xffffffffu, pe0, 1);
            pe0 += __shfl_xor_sync(0xffffffffu, pe0, 2);
            pe1 += __shfl_xor_sync(0xffffffffu, pe1, 1);
            pe1 += __shfl_xor_sync(0xffffffffu, pe1, 2);
            pr0 += __shfl_xor_sync(0xffffffffu, pr0, 1);
            pr0 += __shfl_xor_sync(0xffffffffu, pr0, 2);
            pr1 += __shfl_xor_sync(0xffffffffu, pr1, 1);
            pr1 += __shfl_xor_sync(0xffffffffu, pr1, 2);
            if (tr == 0 && r < Nn) {
                g_el1[r * 8 + 2 * wn]     = pe0;
                g_el1[r * 8 + 2 * wn + 1] = pe1;
                g_er1[r * 8 + 2 * wn]     = pr0;
                g_er1[r * 8 + 2 * wn + 1] = pr1;
            }
        }
    }
}

// ---------------- layer 1 aggregation: warp/dst, 4x unrolled gather --------
__global__ void agg1_kernel(const float* __restrict__ b1) {
    const int wid = (blockIdx.x * blockDim.x + threadIdx.x) >> 5;
    const int lane = threadIdx.x & 31;
    const int d = wid;
    const int rs = g_rowstart[d], re = g_rowstart[d + 1];
    const float erh = (lane < 8) ? g_er1[d * 8 + lane] : 0.f;
    const int h0 = lane >> 4;
    float2 acc[4] = {{0, 0}, {0, 0}, {0, 0}, {0, 0}};
    float s = 0.f;
    int e = rs;
    for (; e + 4 <= re; e += 4) {
        int s0 = g_esrc[e], s1 = g_esrc[e + 1], s2 = g_esrc[e + 2], s3 = g_esrc[e + 3];
        float l0 = 0.f, l1 = 0.f, l2 = 0.f, l3 = 0.f;
        if (lane < 8) {
            l0 = g_el1[s0 * 8 + lane]; l1 = g_el1[s1 * 8 + lane];
            l2 = g_el1[s2 * 8 + lane]; l3 = g_el1[s3 * 8 + lane];
        }
        const __half2* p0 = (const __half2*)(g_h1h + (size_t)s0 * 256);
        const __half2* p1 = (const __half2*)(g_h1h + (size_t)s1 * 256);
        const __half2* p2 = (const __half2*)(g_h1h + (size_t)s2 * 256);
        const __half2* p3 = (const __half2*)(g_h1h + (size_t)s3 * 256);
        __half2 v0[4], v1[4], v2[4], v3[4];
#pragma unroll
        for (int q = 0; q < 4; q++) v0[q] = p0[q * 32 + lane];
#pragma unroll
        for (int q = 0; q < 4; q++) v1[q] = p1[q * 32 + lane];
#pragma unroll
        for (int q = 0; q < 4; q++) v2[q] = p2[q * 32 + lane];
#pragma unroll
        for (int q = 0; q < 4; q++) v3[q] = p3[q * 32 + lane];
        float e0 = 0.f, e1 = 0.f, e2 = 0.f, e3 = 0.f;
        if (lane < 8) {
            e0 = __expf(lrelu(l0 + erh)); e1 = __expf(lrelu(l1 + erh));
            e2 = __expf(lrelu(l2 + erh)); e3 = __expf(lrelu(l3 + erh));
            s += (e0 + e1) + (e2 + e3);
        }
#pragma unroll
        for (int q = 0; q < 4; q++) {
            int hsel = 2 * q + h0;
            float w0 = __shfl_sync(0xffffffffu, e0, hsel);
            float w1 = __shfl_sync(0xffffffffu, e1, hsel);
            float w2 = __shfl_sync(0xffffffffu, e2, hsel);
            float w3 = __shfl_sync(0xffffffffu, e3, hsel);
            float2 f0 = __half22float2(v0[q]), f1 = __half22float2(v1[q]);
            float2 f2 = __half22float2(v2[q]), f3 = __half22float2(v3[q]);
            acc[q].x = fmaf(w0, f0.x, fmaf(w1, f1.x, fmaf(w2, f2.x, fmaf(w3, f3.x, acc[q].x))));
            acc[q].y = fmaf(w0, f0.y, fmaf(w1, f1.y, fmaf(w2, f2.y, fmaf(w3, f3.y, acc[q].y))));
        }
    }
    for (; e < re; e++) {
        int src = g_esrc[e];
        float ee = 0.f;
        if (lane < 8) {
            ee = __expf(lrelu(g_el1[src * 8 + lane] + erh));
            s += ee;
        }
        const __half2* hp = (const __half2*)(g_h1h + (size_t)src * 256);
#pragma unroll
        for (int q = 0; q < 4; q++) {
            float eh = __shfl_sync(0xffffffffu, ee, 2 * q + h0);
            float2 f = __half22float2(hp[q * 32 + lane]);
            acc[q].x = fmaf(eh, f.x, acc[q].x);
            acc[q].y = fmaf(eh, f.y, acc[q].y);
        }
    }
#pragma unroll
    for (int q = 0; q < 4; q++) {
        float sh = __shfl_sync(0xffffffffu, s, 2 * q + h0);
        float inv = (sh > 0.f) ? (1.f / sh) : 0.f;
        int col = 64 * q + 2 * lane;
        float vx = fmaxf(acc[q].x * inv + __ldg(b1 + col), 0.f);
        float vy = fmaxf(acc[q].y * inv + __ldg(b1 + col + 1), 0.f);
        *(float2*)&g_x1[(size_t)d * 256 + col] = make_float2(vx, vy);
    }
}

// ---------------- layer 2 GEMM (TC, bf16 split) + fused el2/er2 ------------
#define A2_STRIDE 260
#define B2_STRIDE 40
#define G2_SMEM ((2 * 64 * A2_STRIDE + 256 * B2_STRIDE) * 4)

__global__ void __launch_bounds__(256) gemm2m_kernel(const float* __restrict__ al,
                                                     const float* __restrict__ ar) {
    extern __shared__ unsigned smem[];
    unsigned* A1 = smem;
    unsigned* A2 = smem + 64 * A2_STRIDE;
    unsigned* B  = smem + 2 * 64 * A2_STRIDE;

    const int t = threadIdx.x;
    const int n0 = blockIdx.x * 64;

#pragma unroll
    for (int i = 0; i < 16; i++) {
        int idx = t + 256 * i;
        int row = idx >> 6, c4 = idx & 63;
        int grow = n0 + row;
        float4 v = (grow < Nn) ? *((const float4*)(g_x1 + (size_t)grow * 256) + c4)
                               : make_float4(0.f, 0.f, 0.f, 0.f);
        float vv[4] = {v.x, v.y, v.z, v.w};
        unsigned p1[4], p2[4];
#pragma unroll
        for (int j = 0; j < 4; j++) splitpack(vv[j], p1[j], p2[j]);
        *(uint4*)&A1[row * A2_STRIDE + c4 * 4] = make_uint4(p1[0], p1[1], p1[2], p1[3]);
        *(uint4*)&A2[row * A2_STRIDE + c4 * 4] = make_uint4(p2[0], p2[1], p2[2], p2[3]);
    }
#pragma unroll
    for (int i = 0; i < 8; i++) {
        int idx = t + 256 * i;
        int row = idx >> 3, c4 = idx & 7;
        uint4 v = *((const uint4*)g_wpk2 + idx);
        *(uint4*)&B[row * B2_STRIDE + c4 * 4] = v;
    }
    __syncthreads();

    const int warp = t >> 5, lane = t & 31;
    const int wm = warp >> 2, wn = warp & 3;
    const int g = lane >> 2, tr = lane & 3;

    float c[2][4] = {};
#pragma unroll 1
    for (int ks = 0; ks < 32; ks++) {
        int kb = ks * 8;
        int col = wn * 8 + g;
        unsigned b0 = B[(kb + tr) * B2_STRIDE + col];
        unsigned b1 = B[(kb + 4 + tr) * B2_STRIDE + col];
#pragma unroll
        for (int pass = 0; pass < 2; pass++) {
            const unsigned* Ap = pass ? A2 : A1;
#pragma unroll
            for (int mt = 0; mt < 2; mt++) {
                int rb = wm * 32 + mt * 16;
                unsigned a0 = Ap[(rb + g) * A2_STRIDE + kb + tr];
                unsigned a1 = Ap[(rb + 8 + g) * A2_STRIDE + kb + tr];
                unsigned a2 = Ap[(rb + g) * A2_STRIDE + kb + 4 + tr];
                unsigned a3 = Ap[(rb + 8 + g) * A2_STRIDE + kb + 4 + tr];
                mma16816(c[mt], a0, a1, a2, a3, b0, b1);
            }
        }
    }
    __syncthreads();

    float* epi_e = (float*)smem;          // [64][4]
    float* epi_r = (float*)smem + 256;    // [64][4]

    const int col = wn * 8 + tr * 2;
    const float a0v = __ldg(al + col), a1v = __ldg(al + col + 1);
    const float r0v = __ldg(ar + col), r1v = __ldg(ar + col + 1);

#pragma unroll
    for (int mt = 0; mt < 2; mt++) {
#pragma unroll
        for (int half = 0; half < 2; half++) {
            int lrow = wm * 32 + mt * 16 + g + 8 * half;
            int r = n0 + lrow;
            float c0 = c[mt][2 * half], c1 = c[mt][2 * half + 1];
            if (r < Nn)
                *(__half2*)&g_h2h[(size_t)r * 32 + col] = __floats2half2_rn(c0, c1);
            float pe = c0 * a0v + c1 * a1v;
            float pr = c0 * r0v + c1 * r1v;
            pe += __shfl_xor_sync(0xffffffffu, pe, 1);
            pe += __shfl_xor_sync(0xffffffffu, pe, 2);
            pr += __shfl_xor_sync(0xffffffffu, pr, 1);
            pr += __shfl_xor_sync(0xffffffffu, pr, 2);
            if (tr == 0) {
                epi_e[lrow * 4 + wn] = pe;
                epi_r[lrow * 4 + wn] = pr;
            }
        }
    }
    __syncthreads();
    if (t < 64) {
        int n = n0 + t;
        if (n < Nn) {
            g_el2[n] = epi_e[t * 4] + epi_e[t * 4 + 1] + epi_e[t * 4 + 2] + epi_e[t * 4 + 3];
            g_er2[n] = epi_r[t * 4] + epi_r[t * 4 + 1] + epi_r[t * 4 + 2] + epi_r[t * 4 + 3];
        }
    }
}

// ---------------- layer 2 aggregation + fused layer-3 projection -----------
__global__ void __launch_bounds__(256) agg2f_kernel(const float* __restrict__ b2,
                                                    float* __restrict__ emb,
                                                    const float* __restrict__ W3,
                                                    const float* __restrict__ al3,
                                                    const float* __restrict__ ar3) {
    __shared__ float W3s[32 * 64];
    __shared__ float al3s[64], ar3s[64];
    const int t = threadIdx.x;
#pragma unroll
    for (int i = 0; i < 8; i++) W3s[t + 256 * i] = __ldg(W3 + t + 256 * i);
    if (t < 64) { al3s[t] = __ldg(al3 + t); ar3s[t] = __ldg(ar3 + t); }
    __syncthreads();

    const int wid = (blockIdx.x * blockDim.x + t) >> 5;
    const int lane = t & 31;
    const int d = wid;
    const int rs = g_rowstart[d], re = g_rowstart[d + 1];
    const float erd = g_er2[d];
    float acc = 0.f, s = 0.f;
    int e = rs;
    for (; e + 8 <= re; e += 8) {
        int si[8];
#pragma unroll
        for (int j = 0; j < 8; j++) si[j] = g_esrc[e + j];
        float lv[8], hv[8];
#pragma unroll
        for (int j = 0; j < 8; j++) lv[j] = g_el2[si[j]];
#pragma unroll
        for (int j = 0; j < 8; j++) hv[j] = __half2float(g_h2h[(size_t)si[j] * 32 + lane]);
#pragma unroll
        for (int j = 0; j < 8; j++) {
            float ee = __expf(lrelu(lv[j] + erd));
            s += ee;
            acc = fmaf(ee, hv[j], acc);
        }
    }
    for (; e < re; e++) {
        int src = g_esrc[e];
        float ee = __expf(lrelu(g_el2[src] + erd));
        s += ee;
        acc = fmaf(ee, __half2float(g_h2h[(size_t)src * 32 + lane]), acc);
    }
    float v = (s > 0.f) ? acc / s : 0.f;
    v += __ldg(b2 + lane);
    emb[(size_t)d * 32 + lane] = v;

    // layer-3 projection
    float a0 = 0.f, a1 = 0.f;
#pragma unroll
    for (int k = 0; k < 32; k++) {
        float ek = __shfl_sync(0xffffffffu, v, k);
        a0 = fmaf(ek, W3s[k * 64 + lane], a0);
        a1 = fmaf(ek, W3s[k * 64 + 32 + lane], a1);
    }
    g_h3h[(size_t)d * 64 + lane]      = __float2half(a0);
    g_h3h[(size_t)d * 64 + 32 + lane] = __float2half(a1);
    float e3 = wred(a0 * al3s[lane] + a1 * al3s[32 + lane]);
    float r3 = wred(a0 * ar3s[lane] + a1 * ar3s[32 + lane]);
    if (lane == 0) { g_el3[d] = e3; g_er3[d] = r3; }
}

// ---------------- layer 3 aggregation: 8x unrolled, half2 gathers ----------
__global__ void agg3_kernel(const float* __restrict__ b3, float* __restrict__ out) {
    const int wid = (blockIdx.x * blockDim.x + threadIdx.x) >> 5;
    const int lane = threadIdx.x & 31;
    const int d = wid;
    const int rs = g_rowstart[d], re = g_rowstart[d + 1];
    const float erd = g_er3[d];
    float ax = 0.f, ay = 0.f, s = 0.f;
    int e = rs;
    for (; e + 8 <= re; e += 8) {
        int si[8];
#pragma unroll
        for (int j = 0; j < 8; j++) si[j] = g_esrc[e + j];
        float lv[8];
        __half2 hv[8];
#pragma unroll
        for (int j = 0; j < 8; j++) lv[j] = g_el3[si[j]];
#pragma unroll
        for (int j = 0; j < 8; j++) hv[j] = *((const __half2*)(g_h3h + (size_t)si[j] * 64) + lane);
#pragma unroll
        for (int j = 0; j < 8; j++) {
            float ee = __expf(lrelu(lv[j] + erd));
            s += ee;
            float2 f = __half22float2(hv[j]);
            ax = fmaf(ee, f.x, ax);
            ay = fmaf(ee, f.y, ay);
        }
    }
    for (; e < re; e++) {
        int src = g_esrc[e];
        float ee = __expf(lrelu(g_el3[src] + erd));
        s += ee;
        float2 f = __half22float2(*((const __half2*)(g_h3h + (size_t)src * 64) + lane));
        ax = fmaf(ee, f.x, ax);
        ay = fmaf(ee, f.y, ay);
    }
    float inv = (s > 0.f) ? (1.f / s) : 0.f;
    int col = 2 * lane;
    float ox = ax * inv + __ldg(b3 + col);
    float oy = ay * inv + __ldg(b3 + col + 1);
    *(float2*)&out[(size_t)d * 64 + col] = make_float2(ox, oy);
}

// ---------------- launch ----------------
extern "C" void kernel_launch(void* const* d_in, const int* in_sizes, int n_in,
                              void* d_out, int out_size) {
    const float* features = (const float*)d_in[0];
    const int*   src      = (const int*)d_in[1];
    const int*   dst      = (const int*)d_in[2];
    const float* W1  = (const float*)d_in[3];
    const float* al1 = (const float*)d_in[4];
    const float* ar1 = (const float*)d_in[5];
    const float* b1  = (const float*)d_in[6];
    const float* W2  = (const float*)d_in[7];
    const float* al2 = (const float*)d_in[8];
    const float* ar2 = (const float*)d_in[9];
    const float* b2  = (const float*)d_in[10];
    const float* W3  = (const float*)d_in[11];
    const float* al3 = (const float*)d_in[12];
    const float* ar3 = (const float*)d_in[13];
    const float* b3  = (const float*)d_in[14];

    float* out = (float*)d_out;                 // h: [N,64]
    float* emb = out + (size_t)Nn * 64;         // embedding: [N,32]

    static cudaStream_t s1 = nullptr;
    static cudaEvent_t ev_fork = nullptr, ev_gemm1 = nullptr;
    if (!s1) {
        cudaFuncSetAttribute(gemm1m_kernel, cudaFuncAttributeMaxDynamicSharedMemorySize, G1_SMEM);
        cudaFuncSetAttribute(gemm2m_kernel, cudaFuncAttributeMaxDynamicSharedMemorySize, G2_SMEM);
        cudaStreamCreate(&s1);
        cudaEventCreateWithFlags(&ev_fork, cudaEventDisableTiming);
        cudaEventCreateWithFlags(&ev_gemm1, cudaEventDisableTiming);
    }

    // Fork: branch A (s1) = weight pack + layer-1 GEMM (independent of graph)
    cudaEventRecord(ev_fork, 0);
    cudaStreamWaitEvent(s1, ev_fork, 0);
    wpack_kernel<<<160, 256, 0, s1>>>(W1, W2);
    gemm1m_kernel<<<(Nn + 63) / 64, 256, G1_SMEM, s1>>>(features, al1, ar1);
    cudaEventRecord(ev_gemm1, s1);

    // Branch B (capture stream) = CSR build
    zero_kernel<<<(Nn + 255) / 256, 256>>>();
    count_kernel<<<(Ne + 255) / 256, 256>>>(dst);
    scan_kernel<<<1, 1024>>>();
    scatter_kernel<<<(Ne + 255) / 256, 256>>>(src, dst);

    // Join: aggregation needs both CSR and gemm1 results
    cudaStreamWaitEvent(0, ev_gemm1, 0);

    agg1_kernel<<<Nn / 8, 256>>>(b1);
    gemm2m_kernel<<<(Nn + 63) / 64, 256, G2_SMEM>>>(al2, ar2);
    agg2f_kernel<<<Nn / 8, 256>>>(b2, emb, W3, al3, ar3);
    agg3_kernel<<<Nn / 8, 256>>>(b3, out);
}